// round 14
// baseline (speedup 1.0000x reference)
#include <cuda_runtime.h>

// B=2, C=4, D=64, H=256, W=256; channels 1..3 of pred/trgt.
// scale(10)/(2*DELTA=10) cancels; vorticity linear -> stencil on (pred-trgt).
// keep voxel <=> min over 3^3 mask neighborhood == 1 (center included).
//
// R14 = R2's scalar kernel (fastest main kernel measured, ~62us) with the
// launch overhead removed: no zero kernel, fused last-block finalize.
// Scalar LDG.32: 1 reg per in-flight load, 1 wavefront per warp-load,
// max occupancy -- empirically 3.8 TB/s vs 3.0-3.1 for all f4 variants.

constexpr int DN = 64, HN = 256, WN = 256;
constexpr long sD = (long)HN * WN;          // 65536
constexpr long sH = WN;                     // 256
constexpr long CS = (long)DN * HN * WN;     // 4194304
constexpr int NPART = 254 * 62 * 2;         // 31496 blocks

__device__ float2 g_part[NPART];
__device__ int g_counter;                   // zero-init; self-resets each launch

// Grid: (254, 62, 2)  block: 256 (threadIdx.x = w, full row).
__global__ __launch_bounds__(256) void vort_kernel(
    const float* __restrict__ pred,
    const float* __restrict__ trgt,
    const float* __restrict__ mask,
    float* __restrict__ out)
{
    const int tid = threadIdx.x;              // w
    const int h   = 1 + blockIdx.x;           // 1..254
    const int d   = 1 + blockIdx.y;           // 1..62
    const int b   = blockIdx.z;

    const long mbase = ((long)b * DN + d) * sD + (long)h * sH + tid;

    // 3x3 (dz,dy) column-min at this w; fully coalesced row loads.
    float cmin = 1e9f;
    #pragma unroll
    for (int dz = -1; dz <= 1; dz++)
        #pragma unroll
        for (int dy = -1; dy <= 1; dy++)
            cmin = fminf(cmin, __ldg(mask + mbase + (long)dz * sD + (long)dy * sH));

    __shared__ float sh_cmin[256];
    sh_cmin[tid] = cmin;
    __syncthreads();

    float numer = 0.0f;
    float den   = 0.0f;

    if (tid >= 1 && tid <= 254) {
        float nmin = fminf(sh_cmin[tid - 1], fminf(cmin, sh_cmin[tid + 1]));
        if (nmin > 0.5f) {                    // keep: center included in min
            den = 1.0f;
            const long pb = (long)b * 4 * CS + (long)d * sD + (long)h * sH + tid;
            const float* pu = pred + pb + 1 * CS;
            const float* pv = pred + pb + 2 * CS;
            const float* pw = pred + pb + 3 * CS;
            const float* tu = trgt + pb + 1 * CS;
            const float* tv = trgt + pb + 2 * CS;
            const float* tw = trgt + pb + 3 * CS;

            float Du_D = (__ldg(pu + sD) - __ldg(tu + sD)) - (__ldg(pu - sD) - __ldg(tu - sD));
            float Du_H = (__ldg(pu + sH) - __ldg(tu + sH)) - (__ldg(pu - sH) - __ldg(tu - sH));
            float Dv_D = (__ldg(pv + sD) - __ldg(tv + sD)) - (__ldg(pv - sD) - __ldg(tv - sD));
            float Dv_W = (__ldg(pv + 1 ) - __ldg(tv + 1 )) - (__ldg(pv - 1 ) - __ldg(tv - 1 ));
            float Dw_H = (__ldg(pw + sH) - __ldg(tw + sH)) - (__ldg(pw - sH) - __ldg(tw - sH));
            float Dw_W = (__ldg(pw + 1 ) - __ldg(tw + 1 )) - (__ldg(pw - 1 ) - __ldg(tw - 1 ));

            float vx = Dw_H - Dv_D;
            float vy = Du_D - Dw_W;
            float vz = Dv_W - Du_H;
            numer = sqrtf(vx * vx + vy * vy + vz * vz);
        }
    }

    // ---- block reduction (8 warps) ----
    const int lane = tid & 31;
    const int wid  = tid >> 5;
    #pragma unroll
    for (int s = 16; s; s >>= 1) {
        numer += __shfl_down_sync(0xffffffffu, numer, s);
        den   += __shfl_down_sync(0xffffffffu, den,   s);
    }
    __shared__ float wn[8], wd[8];
    if (lane == 0) { wn[wid] = numer; wd[wid] = den; }
    __syncthreads();

    __shared__ bool isLast;
    if (wid == 0) {
        float n2 = (lane < 8) ? wn[lane] : 0.0f;
        float d2 = (lane < 8) ? wd[lane] : 0.0f;
        #pragma unroll
        for (int s = 4; s; s >>= 1) {
            n2 += __shfl_down_sync(0xffffffffu, n2, s);
            d2 += __shfl_down_sync(0xffffffffu, d2, s);
        }
        if (lane == 0) {
            const int bid = blockIdx.x + 254 * (blockIdx.y + 62 * blockIdx.z);
            g_part[bid] = make_float2(n2, d2);
            __threadfence();
            int prev = atomicAdd(&g_counter, 1);
            isLast = (prev == NPART - 1);
        }
    }
    __syncthreads();

    // ---- last block finalizes (no tail kernel, no zero kernel) ----
    if (isLast) {
        __threadfence();
        double n = 0.0, dd = 0.0;
        for (int i = tid; i < NPART; i += 256) {
            float2 p = g_part[i];
            n  += (double)p.x;
            dd += (double)p.y;
        }
        #pragma unroll
        for (int s = 16; s; s >>= 1) {
            n  += __shfl_down_sync(0xffffffffu, n,  s);
            dd += __shfl_down_sync(0xffffffffu, dd, s);
        }
        __shared__ double sn[8], sd[8];
        if (lane == 0) { sn[wid] = n; sd[wid] = dd; }
        __syncthreads();
        if (wid == 0) {
            n  = (lane < 8) ? sn[lane] : 0.0;
            dd = (lane < 8) ? sd[lane] : 0.0;
            #pragma unroll
            for (int s = 4; s; s >>= 1) {
                n  += __shfl_down_sync(0xffffffffu, n,  s);
                dd += __shfl_down_sync(0xffffffffu, dd, s);
            }
            if (lane == 0) {
                out[0] = (float)(n / dd);
                g_counter = 0;              // reset for next graph replay
            }
        }
    }
}

extern "C" void kernel_launch(void* const* d_in, const int* in_sizes, int n_in,
                              void* d_out, int out_size) {
    const float* pred = (const float*)d_in[0];   // predicts (2,4,64,256,256)
    const float* trgt = (const float*)d_in[1];   // targets  (2,4,64,256,256)
    const float* mask = (const float*)d_in[2];   // masks    (2,1,64,256,256)
    float* out = (float*)d_out;

    dim3 grid(254, 62, 2);
    vort_kernel<<<grid, 256>>>(pred, trgt, mask, out);
}

// round 15
// speedup vs baseline: 1.3738x; 1.3738x over previous
#include <cuda_runtime.h>

// B=2, C=4, D=64, H=256, W=256; channels 1..3 of pred/trgt.
// scale(10)/(2*DELTA=10) cancels; vorticity linear -> stencil on (pred-trgt).
// keep voxel <=> min over 3^3 mask neighborhood == 1 (center included).
//
// R15 = R14 minus the __threadfence() (gpu-scope fence = CCTL.IVALL = full
// L1D flush per block; 31k flushes destroyed L1 reuse -> 183us vs R2's 62us).
// Ordering now via atom.add.acq_rel.gpu on the counter (no L1 flush) +
// __stcg/__ldcg (L2 path) for the partials.

constexpr int DN = 64, HN = 256, WN = 256;
constexpr long sD = (long)HN * WN;          // 65536
constexpr long sH = WN;                     // 256
constexpr long CS = (long)DN * HN * WN;     // 4194304
constexpr int NPART = 254 * 62 * 2;         // 31496 blocks

__device__ float2 g_part[NPART];
__device__ int g_counter;                   // zero-init; self-resets each launch

__device__ __forceinline__ int atomic_add_acqrel(int* p, int v) {
    int old;
    asm volatile("atom.add.acq_rel.gpu.s32 %0, [%1], %2;"
                 : "=r"(old) : "l"(p), "r"(v) : "memory");
    return old;
}

// Grid: (254, 62, 2)  block: 256 (threadIdx.x = w, full row).
__global__ __launch_bounds__(256) void vort_kernel(
    const float* __restrict__ pred,
    const float* __restrict__ trgt,
    const float* __restrict__ mask,
    float* __restrict__ out)
{
    const int tid = threadIdx.x;              // w
    const int h   = 1 + blockIdx.x;           // 1..254
    const int d   = 1 + blockIdx.y;           // 1..62
    const int b   = blockIdx.z;

    const long mbase = ((long)b * DN + d) * sD + (long)h * sH + tid;

    // 3x3 (dz,dy) column-min at this w; fully coalesced row loads.
    float cmin = 1e9f;
    #pragma unroll
    for (int dz = -1; dz <= 1; dz++)
        #pragma unroll
        for (int dy = -1; dy <= 1; dy++)
            cmin = fminf(cmin, __ldg(mask + mbase + (long)dz * sD + (long)dy * sH));

    __shared__ float sh_cmin[256];
    sh_cmin[tid] = cmin;
    __syncthreads();

    float numer = 0.0f;
    float den   = 0.0f;

    if (tid >= 1 && tid <= 254) {
        float nmin = fminf(sh_cmin[tid - 1], fminf(cmin, sh_cmin[tid + 1]));
        if (nmin > 0.5f) {                    // keep: center included in min
            den = 1.0f;
            const long pb = (long)b * 4 * CS + (long)d * sD + (long)h * sH + tid;
            const float* pu = pred + pb + 1 * CS;
            const float* pv = pred + pb + 2 * CS;
            const float* pw = pred + pb + 3 * CS;
            const float* tu = trgt + pb + 1 * CS;
            const float* tv = trgt + pb + 2 * CS;
            const float* tw = trgt + pb + 3 * CS;

            float Du_D = (__ldg(pu + sD) - __ldg(tu + sD)) - (__ldg(pu - sD) - __ldg(tu - sD));
            float Du_H = (__ldg(pu + sH) - __ldg(tu + sH)) - (__ldg(pu - sH) - __ldg(tu - sH));
            float Dv_D = (__ldg(pv + sD) - __ldg(tv + sD)) - (__ldg(pv - sD) - __ldg(tv - sD));
            float Dv_W = (__ldg(pv + 1 ) - __ldg(tv + 1 )) - (__ldg(pv - 1 ) - __ldg(tv - 1 ));
            float Dw_H = (__ldg(pw + sH) - __ldg(tw + sH)) - (__ldg(pw - sH) - __ldg(tw - sH));
            float Dw_W = (__ldg(pw + 1 ) - __ldg(tw + 1 )) - (__ldg(pw - 1 ) - __ldg(tw - 1 ));

            float vx = Dw_H - Dv_D;
            float vy = Du_D - Dw_W;
            float vz = Dv_W - Du_H;
            numer = sqrtf(vx * vx + vy * vy + vz * vz);
        }
    }

    // ---- block reduction (8 warps) ----
    const int lane = tid & 31;
    const int wid  = tid >> 5;
    #pragma unroll
    for (int s = 16; s; s >>= 1) {
        numer += __shfl_down_sync(0xffffffffu, numer, s);
        den   += __shfl_down_sync(0xffffffffu, den,   s);
    }
    __shared__ float wn[8], wd[8];
    if (lane == 0) { wn[wid] = numer; wd[wid] = den; }
    __syncthreads();

    __shared__ bool isLast;
    if (wid == 0) {
        float n2 = (lane < 8) ? wn[lane] : 0.0f;
        float d2 = (lane < 8) ? wd[lane] : 0.0f;
        #pragma unroll
        for (int s = 4; s; s >>= 1) {
            n2 += __shfl_down_sync(0xffffffffu, n2, s);
            d2 += __shfl_down_sync(0xffffffffu, d2, s);
        }
        if (lane == 0) {
            const int bid = blockIdx.x + 254 * (blockIdx.y + 62 * blockIdx.z);
            __stcg(&g_part[bid], make_float2(n2, d2));     // L2-resident partial
            // release: orders the partial store; acquire: for the last block's
            // reads. NO gpu-scope fence -> no CCTL.IVALL L1 flush.
            int prev = atomic_add_acqrel(&g_counter, 1);
            isLast = (prev == NPART - 1);
        }
    }
    __syncthreads();

    // ---- last block finalizes (no tail kernel, no zero kernel) ----
    if (isLast) {
        double n = 0.0, dd = 0.0;
        for (int i = tid; i < NPART; i += 256) {
            float2 p = __ldcg(&g_part[i]);                 // L2 path, never stale
            n  += (double)p.x;
            dd += (double)p.y;
        }
        #pragma unroll
        for (int s = 16; s; s >>= 1) {
            n  += __shfl_down_sync(0xffffffffu, n,  s);
            dd += __shfl_down_sync(0xffffffffu, dd, s);
        }
        __shared__ double sn[8], sd[8];
        if (lane == 0) { sn[wid] = n; sd[wid] = dd; }
        __syncthreads();
        if (wid == 0) {
            n  = (lane < 8) ? sn[lane] : 0.0;
            dd = (lane < 8) ? sd[lane] : 0.0;
            #pragma unroll
            for (int s = 4; s; s >>= 1) {
                n  += __shfl_down_sync(0xffffffffu, n,  s);
                dd += __shfl_down_sync(0xffffffffu, dd, s);
            }
            if (lane == 0) {
                out[0] = (float)(n / dd);
                int zero = 0;
                __stcg(&g_counter, zero);                  // reset for next replay
            }
        }
    }
}

extern "C" void kernel_launch(void* const* d_in, const int* in_sizes, int n_in,
                              void* d_out, int out_size) {
    const float* pred = (const float*)d_in[0];   // predicts (2,4,64,256,256)
    const float* trgt = (const float*)d_in[1];   // targets  (2,4,64,256,256)
    const float* mask = (const float*)d_in[2];   // masks    (2,1,64,256,256)
    float* out = (float*)d_out;

    dim3 grid(254, 62, 2);
    vort_kernel<<<grid, 256>>>(pred, trgt, mask, out);
}

// round 16
// speedup vs baseline: 2.4811x; 1.8061x over previous
#include <cuda_runtime.h>

// B=2, C=4, D=64, H=256, W=256; channels 1..3 of pred/trgt.
// scale(10)/(2*DELTA=10) cancels; vorticity linear -> stencil on (pred-trgt).
// keep voxel <=> min over 3^3 mask neighborhood == 1 (center included).
//
// R16 = R2's scalar engine (fastest measured: ~62us, 3.8 TB/s) with launch
// overhead minimized. NO gpu-scope fences/acquires anywhere in the hot kernel
// (R14/R15 proved they flush/invalidate L1 per block: 183/133us).
// Plain relaxed atomicAdd -> 256 spread slots; kernel boundary provides
// ordering; finalize kernel self-resets the slots for graph replay.

constexpr int DN = 64, HN = 256, WN = 256;
constexpr long sD = (long)HN * WN;          // 65536
constexpr long sH = WN;                     // 256
constexpr long CS = (long)DN * HN * WN;     // 4194304
#define NSLOTS 256

__device__ double g_num[NSLOTS];            // zero at load; finalize re-zeros
__device__ double g_den[NSLOTS];

// Grid: (254, 62, 2)  block: 256 (threadIdx.x = w, full row).
__global__ __launch_bounds__(256) void vort_kernel(
    const float* __restrict__ pred,
    const float* __restrict__ trgt,
    const float* __restrict__ mask)
{
    const int tid = threadIdx.x;              // w
    const int h   = 1 + blockIdx.x;           // 1..254
    const int d   = 1 + blockIdx.y;           // 1..62
    const int b   = blockIdx.z;

    const long mbase = ((long)b * DN + d) * sD + (long)h * sH + tid;

    // 3x3 (dz,dy) column-min at this w; fully coalesced row loads.
    float cmin = 1e9f;
    #pragma unroll
    for (int dz = -1; dz <= 1; dz++)
        #pragma unroll
        for (int dy = -1; dy <= 1; dy++)
            cmin = fminf(cmin, __ldg(mask + mbase + (long)dz * sD + (long)dy * sH));

    __shared__ float sh_cmin[256];
    sh_cmin[tid] = cmin;
    __syncthreads();

    float numer = 0.0f;
    float den   = 0.0f;

    if (tid >= 1 && tid <= 254) {
        float nmin = fminf(sh_cmin[tid - 1], fminf(cmin, sh_cmin[tid + 1]));
        if (nmin > 0.5f) {                    // keep: center included in min
            den = 1.0f;
            const long pb = (long)b * 4 * CS + (long)d * sD + (long)h * sH + tid;
            const float* pu = pred + pb + 1 * CS;
            const float* pv = pred + pb + 2 * CS;
            const float* pw = pred + pb + 3 * CS;
            const float* tu = trgt + pb + 1 * CS;
            const float* tv = trgt + pb + 2 * CS;
            const float* tw = trgt + pb + 3 * CS;

            float Du_D = (__ldg(pu + sD) - __ldg(tu + sD)) - (__ldg(pu - sD) - __ldg(tu - sD));
            float Du_H = (__ldg(pu + sH) - __ldg(tu + sH)) - (__ldg(pu - sH) - __ldg(tu - sH));
            float Dv_D = (__ldg(pv + sD) - __ldg(tv + sD)) - (__ldg(pv - sD) - __ldg(tv - sD));
            float Dv_W = (__ldg(pv + 1 ) - __ldg(tv + 1 )) - (__ldg(pv - 1 ) - __ldg(tv - 1 ));
            float Dw_H = (__ldg(pw + sH) - __ldg(tw + sH)) - (__ldg(pw - sH) - __ldg(tw - sH));
            float Dw_W = (__ldg(pw + 1 ) - __ldg(tw + 1 )) - (__ldg(pw - 1 ) - __ldg(tw - 1 ));

            float vx = Dw_H - Dv_D;
            float vy = Du_D - Dw_W;
            float vz = Dv_W - Du_H;
            numer = sqrtf(vx * vx + vy * vy + vz * vz);
        }
    }

    // ---- block reduction (8 warps), then one relaxed atomic pair ----
    const int lane = tid & 31;
    const int wid  = tid >> 5;
    #pragma unroll
    for (int s = 16; s; s >>= 1) {
        numer += __shfl_down_sync(0xffffffffu, numer, s);
        den   += __shfl_down_sync(0xffffffffu, den,   s);
    }
    __shared__ float wn[8], wd[8];
    if (lane == 0) { wn[wid] = numer; wd[wid] = den; }
    __syncthreads();
    if (wid == 0) {
        float n2 = (lane < 8) ? wn[lane] : 0.0f;
        float d2 = (lane < 8) ? wd[lane] : 0.0f;
        #pragma unroll
        for (int s = 4; s; s >>= 1) {
            n2 += __shfl_down_sync(0xffffffffu, n2, s);
            d2 += __shfl_down_sync(0xffffffffu, d2, s);
        }
        if (lane == 0) {
            int slot = (int)((blockIdx.x + 254 * (blockIdx.y + 62 * blockIdx.z))
                             & (NSLOTS - 1));
            atomicAdd(&g_num[slot], (double)n2);   // relaxed RED.ADD -> L2 only
            atomicAdd(&g_den[slot], (double)d2);
        }
    }
}

// Tiny finalize: sums 256 slots, writes result, re-zeros slots for next replay.
__global__ void finalize_kernel(float* __restrict__ out) {
    const int t = threadIdx.x;
    double n = g_num[t];
    double d = g_den[t];
    g_num[t] = 0.0;                           // self-reset (own slot; no race)
    g_den[t] = 0.0;

    const int lane = t & 31, wid = t >> 5;
    #pragma unroll
    for (int s = 16; s; s >>= 1) {
        n += __shfl_down_sync(0xffffffffu, n, s);
        d += __shfl_down_sync(0xffffffffu, d, s);
    }
    __shared__ double sn[8], sd[8];
    if (lane == 0) { sn[wid] = n; sd[wid] = d; }
    __syncthreads();
    if (wid == 0) {
        n = (lane < 8) ? sn[lane] : 0.0;
        d = (lane < 8) ? sd[lane] : 0.0;
        #pragma unroll
        for (int s = 4; s; s >>= 1) {
            n += __shfl_down_sync(0xffffffffu, n, s);
            d += __shfl_down_sync(0xffffffffu, d, s);
        }
        if (lane == 0) out[0] = (float)(n / d);
    }
}

extern "C" void kernel_launch(void* const* d_in, const int* in_sizes, int n_in,
                              void* d_out, int out_size) {
    const float* pred = (const float*)d_in[0];   // predicts (2,4,64,256,256)
    const float* trgt = (const float*)d_in[1];   // targets  (2,4,64,256,256)
    const float* mask = (const float*)d_in[2];   // masks    (2,1,64,256,256)
    float* out = (float*)d_out;

    dim3 grid(254, 62, 2);
    vort_kernel<<<grid, 256>>>(pred, trgt, mask);
    finalize_kernel<<<1, NSLOTS>>>(out);
}

// round 17
// speedup vs baseline: 2.7776x; 1.1195x over previous
#include <cuda_runtime.h>

// B=2, C=4, D=64, H=256, W=256; channels 1..3 of pred/trgt.
// scale(10)/(2*DELTA=10) cancels; vorticity linear -> stencil on (pred-trgt).
// keep voxel <=> min over 3^3 mask neighborhood == 1 (center included).
//
// R17 = R16 scalar engine + h-pairing: each block does 2 adjacent h rows.
// The 3x3 (dz,dy) mask column-mins for the two rows share their middle
// y-rows: 12 mask loads serve 2 voxels (6/voxel vs 9/voxel).
// Mask loads are ~87% of load instructions (keep-rate 5.8% makes the
// 24-tap stencil conditional path cheap), so this attacks the dominant stream.
// No gpu-scope fences/acquires in the hot kernel (R14/R15: L1 poison).

constexpr int DN = 64, HN = 256, WN = 256;
constexpr long sD = (long)HN * WN;          // 65536
constexpr long sH = WN;                     // 256
constexpr long CS = (long)DN * HN * WN;     // 4194304
#define NSLOTS 256

__device__ double g_num[NSLOTS];            // zero at load; finalize re-zeros
__device__ double g_den[NSLOTS];

// Grid: (127, 62, 2)  block: 256 (threadIdx.x = w; 2 h rows per block).
__global__ __launch_bounds__(256) void vort_kernel(
    const float* __restrict__ pred,
    const float* __restrict__ trgt,
    const float* __restrict__ mask)
{
    const int tid = threadIdx.x;              // w
    const int h0  = 1 + 2 * blockIdx.x;       // 1,3,...,253 ; rows h0, h0+1
    const int d   = 1 + blockIdx.y;           // 1..62
    const int b   = blockIdx.z;

    // z-column mins for 4 y-rows (h0-1 .. h0+2): 12 coalesced loads.
    const long mb = ((long)b * DN + d) * sD + (long)(h0 - 1) * sH + tid;
    float ym0, ym1, ym2, ym3;
    {
        const float* p0 = mask + mb - sD;     // z = d-1
        const float* p1 = mask + mb;          // z = d
        const float* p2 = mask + mb + sD;     // z = d+1
        ym0 = fminf(__ldg(p0         ), fminf(__ldg(p1         ), __ldg(p2         )));
        ym1 = fminf(__ldg(p0 +     sH), fminf(__ldg(p1 +     sH), __ldg(p2 +     sH)));
        ym2 = fminf(__ldg(p0 + 2 * sH), fminf(__ldg(p1 + 2 * sH), __ldg(p2 + 2 * sH)));
        ym3 = fminf(__ldg(p0 + 3 * sH), fminf(__ldg(p1 + 3 * sH), __ldg(p2 + 3 * sH)));
    }
    const float cmin0 = fminf(ym0, fminf(ym1, ym2));   // row h0
    const float cmin1 = fminf(ym1, fminf(ym2, ym3));   // row h0+1

    __shared__ float sh[2][256];
    sh[0][tid] = cmin0;
    sh[1][tid] = cmin1;
    __syncthreads();

    float numer = 0.0f;
    float den   = 0.0f;

    if (tid >= 1 && tid <= 254) {
        #pragma unroll
        for (int r = 0; r < 2; r++) {
            const float cmr = (r == 0) ? cmin0 : cmin1;
            float nmin = fminf(sh[r][tid - 1], fminf(cmr, sh[r][tid + 1]));
            if (nmin > 0.5f) {                // keep: center included in min
                den += 1.0f;
                const int h = h0 + r;
                const long pb = (long)b * 4 * CS + (long)d * sD + (long)h * sH + tid;
                const float* pu = pred + pb + 1 * CS;
                const float* pv = pred + pb + 2 * CS;
                const float* pw = pred + pb + 3 * CS;
                const float* tu = trgt + pb + 1 * CS;
                const float* tv = trgt + pb + 2 * CS;
                const float* tw = trgt + pb + 3 * CS;

                float Du_D = (__ldg(pu + sD) - __ldg(tu + sD)) - (__ldg(pu - sD) - __ldg(tu - sD));
                float Du_H = (__ldg(pu + sH) - __ldg(tu + sH)) - (__ldg(pu - sH) - __ldg(tu - sH));
                float Dv_D = (__ldg(pv + sD) - __ldg(tv + sD)) - (__ldg(pv - sD) - __ldg(tv - sD));
                float Dv_W = (__ldg(pv + 1 ) - __ldg(tv + 1 )) - (__ldg(pv - 1 ) - __ldg(tv - 1 ));
                float Dw_H = (__ldg(pw + sH) - __ldg(tw + sH)) - (__ldg(pw - sH) - __ldg(tw - sH));
                float Dw_W = (__ldg(pw + 1 ) - __ldg(tw + 1 )) - (__ldg(pw - 1 ) - __ldg(tw - 1 ));

                float vx = Dw_H - Dv_D;
                float vy = Du_D - Dw_W;
                float vz = Dv_W - Du_H;
                numer += sqrtf(vx * vx + vy * vy + vz * vz);
            }
        }
    }

    // ---- block reduction (8 warps), then one relaxed atomic pair ----
    const int lane = tid & 31;
    const int wid  = tid >> 5;
    #pragma unroll
    for (int s = 16; s; s >>= 1) {
        numer += __shfl_down_sync(0xffffffffu, numer, s);
        den   += __shfl_down_sync(0xffffffffu, den,   s);
    }
    __shared__ float wn[8], wd[8];
    if (lane == 0) { wn[wid] = numer; wd[wid] = den; }
    __syncthreads();
    if (wid == 0) {
        float n2 = (lane < 8) ? wn[lane] : 0.0f;
        float d2 = (lane < 8) ? wd[lane] : 0.0f;
        #pragma unroll
        for (int s = 4; s; s >>= 1) {
            n2 += __shfl_down_sync(0xffffffffu, n2, s);
            d2 += __shfl_down_sync(0xffffffffu, d2, s);
        }
        if (lane == 0) {
            int slot = (int)((blockIdx.x + 127 * (blockIdx.y + 62 * blockIdx.z))
                             & (NSLOTS - 1));
            atomicAdd(&g_num[slot], (double)n2);   // relaxed RED.ADD -> L2 only
            atomicAdd(&g_den[slot], (double)d2);
        }
    }
}

// Tiny finalize: sums 256 slots, writes result, re-zeros slots for next replay.
__global__ void finalize_kernel(float* __restrict__ out) {
    const int t = threadIdx.x;
    double n = g_num[t];
    double d = g_den[t];
    g_num[t] = 0.0;                           // self-reset (own slot; no race)
    g_den[t] = 0.0;

    const int lane = t & 31, wid = t >> 5;
    #pragma unroll
    for (int s = 16; s; s >>= 1) {
        n += __shfl_down_sync(0xffffffffu, n, s);
        d += __shfl_down_sync(0xffffffffu, d, s);
    }
    __shared__ double sn[8], sd[8];
    if (lane == 0) { sn[wid] = n; sd[wid] = d; }
    __syncthreads();
    if (wid == 0) {
        n = (lane < 8) ? sn[lane] : 0.0;
        d = (lane < 8) ? sd[lane] : 0.0;
        #pragma unroll
        for (int s = 4; s; s >>= 1) {
            n += __shfl_down_sync(0xffffffffu, n, s);
            d += __shfl_down_sync(0xffffffffu, d, s);
        }
        if (lane == 0) out[0] = (float)(n / d);
    }
}

extern "C" void kernel_launch(void* const* d_in, const int* in_sizes, int n_in,
                              void* d_out, int out_size) {
    const float* pred = (const float*)d_in[0];   // predicts (2,4,64,256,256)
    const float* trgt = (const float*)d_in[1];   // targets  (2,4,64,256,256)
    const float* mask = (const float*)d_in[2];   // masks    (2,1,64,256,256)
    float* out = (float*)d_out;

    dim3 grid(127, 62, 2);
    vort_kernel<<<grid, 256>>>(pred, trgt, mask);
    finalize_kernel<<<1, NSLOTS>>>(out);
}